// round 5
// baseline (speedup 1.0000x reference)
#include <cuda_runtime.h>
#include <cuda_bf16.h>
#include <mma.h>
#include <math.h>

using namespace nvcuda;

#define BATCH 8192
#define SDIM  376
#define ADIM  17
#define DIN   393
#define DPAD  416           // padded K: 13 chunks of 32
#define KCH   32
#define NCHK  13
#define H1    400
#define NPAD  448           // padded N (4 col-sets of 112 = 7 frags)
#define SBST  456           // B smem stride (odd multiple of 8 -> conflict-free)
#define SAST  40            // A smem stride
#define H2    300
#define TSTEPS 32

#define CAPC  24
#define CAP1  96
#define CAP2  96

// ---------------- static device scratch ----------------
__device__ __align__(16) __nv_bfloat16 g_A[(size_t)BATCH * DPAD];
__device__ __align__(16) __nv_bfloat16 g_W1p[(size_t)DPAD * NPAD];
__device__ __align__(16) unsigned      g_S1[(size_t)BATCH * H1];   // only slow rows
__device__ float g_c[H1];          // c_i = max_j W2[i,j]
__device__ float g_b2max;
__device__ float g_const[ADIM];    // 0.05*tanh(vmax(b3_k))
__device__ int   g_nslow;
__device__ int   g_slowlist[BATCH];

// ---------------- cp.async helpers ----------------
__device__ __forceinline__ void cp16(void* dst, const void* src) {
    unsigned d = (unsigned)__cvta_generic_to_shared(dst);
    asm volatile("cp.async.cg.shared.global [%0], [%1], 16;\n" :: "r"(d), "l"(src));
}
__device__ __forceinline__ void cp_commit() {
    asm volatile("cp.async.commit_group;\n");
}
template<int N> __device__ __forceinline__ void cp_wait() {
    asm volatile("cp.async.wait_group %0;\n" :: "n"(N));
}

// ---------------- K0a: pack [state|action|0pad] -> bf16 ----------------
__global__ void k_pack_input(const float* __restrict__ state,
                             const float* __restrict__ action) {
    int idx = blockIdx.x * blockDim.x + threadIdx.x;     // one per 8 cols
    if (idx >= BATCH * (DPAD / 8)) return;
    int row = idx / (DPAD / 8);
    int c0  = (idx - row * (DPAD / 8)) * 8;
    __nv_bfloat16 v[8];
#pragma unroll
    for (int u = 0; u < 8; u++) {
        int col = c0 + u;
        float f = 0.0f;
        if (col < SDIM)      f = state[(size_t)row * SDIM + col];
        else if (col < DIN)  f = action[(size_t)row * ADIM + (col - SDIM)];
        v[u] = __float2bfloat16(f);
    }
    *reinterpret_cast<uint4*>(&g_A[(size_t)row * DPAD + c0]) =
        *reinterpret_cast<uint4*>(v);
}

// ---------------- K0b: pack W1 -> [416][448] bf16, zero pad ----------------
__global__ void k_pack_w1(const float* __restrict__ W1) {
    int idx = blockIdx.x * blockDim.x + threadIdx.x;
    if (idx >= DPAD * NPAD) return;
    int r = idx / NPAD;
    int c = idx - r * NPAD;
    float f = (r < DIN && c < H1) ? W1[(size_t)r * H1 + c] : 0.0f;
    g_W1p[idx] = __float2bfloat16(f);
}

// ---------------- K_prep: c_i, b2max, const_k, reset list ----------------
__global__ void k_prep(const float* __restrict__ W2,
                       const float* __restrict__ b2,
                       const float* __restrict__ b3) {
    int bid  = blockIdx.x;
    int lane = threadIdx.x;
    if (bid < H1) {
        float m = -3.4e38f;
        for (int j = lane; j < H2; j += 32)
            m = fmaxf(m, W2[(size_t)bid * H2 + j]);
#pragma unroll
        for (int o = 16; o; o >>= 1) m = fmaxf(m, __shfl_xor_sync(0xffffffffu, m, o));
        if (lane == 0) g_c[bid] = m;
    } else {
        float m = -3.4e38f;
        for (int j = lane; j < H2; j += 32) m = fmaxf(m, b2[j]);
#pragma unroll
        for (int o = 16; o; o >>= 1) m = fmaxf(m, __shfl_xor_sync(0xffffffffu, m, o));
        if (lane == 0) g_b2max = m;
        if (lane == 20) g_nslow = 0;
        if (lane < ADIM) {
            float b = b3[lane];
            float vmax = (b > 0.0f) ? b : 0.5f * b;   // monotone v3 = b3*(1-2^-t)
            g_const[lane] = 0.05f * tanhf(vmax);
        }
    }
}

// ---------------- K1: fused GEMM + LIF1 + bound-check + fast output --------
// tile: 32 rows x 448 cols (full width). 256 threads = 8 warps:
//   warp w: rowgroup rg=w>>2 (16 rows), colset cs=w&3 (7 frags of 16 = 112 cols)
// dynamic smem: [A dbuf 5120B][B dbuf 58368B]; fp32 stage (58368B) overlays.
__global__ __launch_bounds__(256, 2) void k_fused(const float* __restrict__ b1,
                                                  const float* __restrict__ action,
                                                  float* __restrict__ out) {
    extern __shared__ __align__(16) unsigned char sm[];
    __nv_bfloat16* sA0 = reinterpret_cast<__nv_bfloat16*>(sm);
    __nv_bfloat16* sA1 = sA0 + 32 * SAST;
    __nv_bfloat16* sB0 = reinterpret_cast<__nv_bfloat16*>(sm + 5120);
    __nv_bfloat16* sB1 = sB0 + KCH * SBST;
    __nv_bfloat16* sAp[2] = { sA0, sA1 };
    __nv_bfloat16* sBp[2] = { sB0, sB1 };
    float*    stage   = reinterpret_cast<float*>(sm);
    unsigned* stage_u = reinterpret_cast<unsigned*>(sm);

    __shared__ float s_c[H1];
    __shared__ float s_b1[H1];
    __shared__ float s_const[ADIM];
    __shared__ float s_b2max;

    const int tid  = threadIdx.x;
    const int lane = tid & 31;
    const int w    = tid >> 5;
    const int rg   = w >> 2;
    const int cs   = w & 3;
    const int m0   = blockIdx.x * 32;

    // prefetch small constants (FIX: strided loop, H1 > blockDim)
    for (int i = tid; i < H1; i += 256) { s_c[i] = g_c[i]; s_b1[i] = b1[i]; }
    if (tid < ADIM) s_const[tid] = g_const[tid];
    if (tid == 32)  s_b2max = g_b2max;

    wmma::fragment<wmma::accumulator, 16, 16, 16, float> acc[7];
#pragma unroll
    for (int f = 0; f < 7; f++) wmma::fill_fragment(acc[f], 0.0f);

    auto load_chunk = [&](int c, int b) {
        // A: 32 rows x 32 k  -> 128 cp16
        if (tid < 128) {
            int r = tid >> 2, h = tid & 3;
            cp16(sAp[b] + r * SAST + 8 * h,
                 &g_A[(size_t)(m0 + r) * DPAD + c * KCH + 8 * h]);
        }
        // B: 32 k-rows x 448 cols -> 1792 cp16 (7 per thread)
#pragma unroll
        for (int rep = 0; rep < 7; rep++) {
            int t2 = tid + rep * 256;
            int r = t2 / 56, p = t2 - r * 56;
            cp16(sBp[b] + r * SBST + 8 * p,
                 &g_W1p[(size_t)(c * KCH + r) * NPAD + 8 * p]);
        }
    };

    load_chunk(0, 0);
    cp_commit();

    for (int c = 0; c < NCHK; c++) {
        int cur = c & 1;
        if (c + 1 < NCHK) {
            load_chunk(c + 1, cur ^ 1);
            cp_commit();
            cp_wait<1>();
        } else {
            cp_wait<0>();
        }
        __syncthreads();

#pragma unroll
        for (int ks = 0; ks < 2; ks++) {
            wmma::fragment<wmma::matrix_a, 16, 16, 16, __nv_bfloat16, wmma::row_major> afrag;
            wmma::load_matrix_sync(afrag, sAp[cur] + (rg * 16) * SAST + ks * 16, SAST);
#pragma unroll
            for (int f = 0; f < 7; f++) {
                wmma::fragment<wmma::matrix_b, 16, 16, 16, __nv_bfloat16, wmma::row_major> bfrag;
                wmma::load_matrix_sync(bfrag,
                    sBp[cur] + (ks * 16) * SBST + cs * 112 + f * 16, SBST);
                wmma::mma_sync(acc[f], afrag, bfrag, acc[f]);
            }
        }
        __syncthreads();
    }

    // ---- epilogue: stage fp32, LIF per element (in-place word), check ----
#pragma unroll
    for (int f = 0; f < 7; f++)
        wmma::store_matrix_sync(&stage[(rg * 16) * SBST + cs * 112 + f * 16],
                                acc[f], SBST, wmma::mem_row_major);
    __syncthreads();

    for (int idx = tid; idx < 32 * H1; idx += 256) {
        int r = idx / H1;
        int c = idx - r * H1;
        float x = stage[r * SBST + c] + s_b1[c];
        unsigned word = 0u;
        if (x >= 0.999999f) {              // v_t < x always: x<1 can't spike
            float v = 0.0f;
#pragma unroll
            for (int t = 0; t < TSTEPS; t++) {
                v = fmaf(x - v, 0.5f, v);
                if (v >= 1.0f) { word |= (1u << t); v = 0.0f; }
            }
        }
        stage_u[r * SBST + c] = word;
    }
    __syncthreads();

    // per-row check: warp w handles rows w*4 .. w*4+3
#pragma unroll
    for (int rr = 0; rr < 4; rr++) {
        int r = w * 4 + rr;
        int grow = m0 + r;
        float accu = 0.0f;                 // lane = timestep
        for (int ch = 0; ch < 13; ch++) {
            int i = ch * 32 + lane;
            unsigned word = (i < H1) ? stage_u[r * SBST + i] : 0u;
            unsigned bal = __ballot_sync(0xffffffffu, word != 0u);
            while (bal) {
                int b = __ffs(bal) - 1;
                bal &= bal - 1;
                unsigned wb = __shfl_sync(0xffffffffu, word, b);
                float ci = s_c[ch * 32 + b];
                if ((wb >> lane) & 1u) accu += ci;
            }
        }
        float m = accu;
#pragma unroll
        for (int o = 16; o; o >>= 1) m = fmaxf(m, __shfl_xor_sync(0xffffffffu, m, o));
        int slow = (s_b2max + m >= 1.0f);

        if (!slow) {
            if (lane < ADIM) {
                float o = s_const[lane] + action[(size_t)grow * ADIM + lane];
                out[(size_t)grow * ADIM + lane] = fminf(fmaxf(o, -1.0f), 1.0f);
            }
        } else {
            for (int ch = 0; ch < 13; ch++) {
                int i = ch * 32 + lane;
                if (i < H1)
                    g_S1[(size_t)grow * H1 + i] = stage_u[r * SBST + i];
            }
            if (lane == 0) {
                int s = atomicAdd(&g_nslow, 1);
                g_slowlist[s] = grow;
            }
        }
    }
}

// ---------------- K2: exact slow path over compact list ----------------
__global__ __launch_bounds__(320) void k_snn(const float* __restrict__ action,
                                             const float* __restrict__ W2,
                                             const float* __restrict__ b2,
                                             const float* __restrict__ W3,
                                             const float* __restrict__ b3,
                                             float* __restrict__ out) {
    __shared__ float          s_w2[CAPC * H2];
    __shared__ unsigned       s_mask1[H1];
    __shared__ unsigned short s_fire[H1];
    __shared__ unsigned short s_list1[TSTEPS][CAP1];
    __shared__ int            s_cnt1[TSTEPS];
    __shared__ unsigned       s_mask2[H2];
    __shared__ unsigned short s_list2[TSTEPS][CAP2];
    __shared__ int            s_cnt2[TSTEPS];
    __shared__ int            s_nf;

    int tid  = threadIdx.x;
    int lane = tid & 31;
    int w    = tid >> 5;
    unsigned lmask = (1u << lane) - 1u;
    int nslow = g_nslow;

    for (int s = blockIdx.x; s < nslow; s += gridDim.x) {
        int row = g_slowlist[s];

        for (int i = tid; i < H1; i += 320)
            s_mask1[i] = g_S1[(size_t)row * H1 + i];
        __syncthreads();

        if (w == 0) {
            int nf = 0;
            for (int c = 0; c * 32 < H1; c++) {
                int i = c * 32 + lane;
                unsigned m = (i < H1) ? s_mask1[i] : 0u;
                int pred = (m != 0u);
                unsigned bal = __ballot_sync(0xffffffffu, pred);
                int pos = nf + __popc(bal & lmask);
                if (pred) s_fire[pos] = (unsigned short)i;
                nf += __popc(bal);
            }
            if (lane == 0) s_nf = nf;
        }
        __syncthreads();
        int nf = s_nf;
        int ncache = nf < CAPC ? nf : CAPC;

        for (int idx = tid; idx < ncache * H2; idx += 320) {
            int q = idx / H2;
            int j = idx - q * H2;
            s_w2[q * H2 + j] = W2[(size_t)s_fire[q] * H2 + j];
        }

        for (int t = w; t < TSTEPS; t += 10) {
            int cnt = 0;
            for (int c = 0; c * 32 < nf; c++) {
                int qi = c * 32 + lane;
                int pred = 0; unsigned short entry = 0;
                if (qi < nf) {
                    int i = s_fire[qi];
                    if ((s_mask1[i] >> t) & 1u) {
                        pred = 1;
                        entry = (qi < CAPC) ? (unsigned short)qi
                                            : (unsigned short)(256 + i);
                    }
                }
                unsigned bal = __ballot_sync(0xffffffffu, pred);
                int pos = cnt + __popc(bal & lmask);
                if (pred && pos < CAP1) s_list1[t][pos] = entry;
                cnt += __popc(bal);
            }
            s_cnt1[t] = cnt < CAP1 ? cnt : CAP1;
        }
        __syncthreads();

        if (tid < H2) {
            int j = tid;
            float b2j = b2[j];
            float v2 = 0.0f;
            unsigned mask2 = 0u;
            for (int t = 0; t < TSTEPS; t++) {
                float x2 = b2j;
                int n = s_cnt1[t];
                for (int q = 0; q < n; q++) {
                    int e = s_list1[t][q];
                    float wv = (e < CAPC) ? s_w2[e * H2 + j]
                                          : W2[(size_t)(e - 256) * H2 + j];
                    x2 += wv;
                }
                v2 += (x2 - v2) * 0.5f;
                if (v2 >= 1.0f) { mask2 |= (1u << t); v2 = 0.0f; }
            }
            s_mask2[j] = mask2;
        }
        __syncthreads();

        for (int t = w; t < TSTEPS; t += 10) {
            int cnt = 0;
            for (int c = 0; c * 32 < H2; c++) {
                int j = c * 32 + lane;
                int pred = 0;
                if (j < H2) pred = (int)((s_mask2[j] >> t) & 1u);
                unsigned bal = __ballot_sync(0xffffffffu, pred);
                int pos = cnt + __popc(bal & lmask);
                if (pred && pos < CAP2) s_list2[t][pos] = (unsigned short)j;
                cnt += __popc(bal);
            }
            s_cnt2[t] = cnt < CAP2 ? cnt : CAP2;
        }
        __syncthreads();

        if (tid < ADIM) {
            int k = tid;
            float b3k = b3[k];
            float v3 = 0.0f, vmax = -3.4e38f;
            for (int t = 0; t < TSTEPS; t++) {
                float x3 = b3k;
                int n = s_cnt2[t];
                for (int q = 0; q < n; q++) {
                    int j = s_list2[t][q];
                    x3 += W3[j * ADIM + k];
                }
                v3 += (x3 - v3) * 0.5f;
                vmax = fmaxf(vmax, v3);
            }
            float a = 0.05f * tanhf(vmax);
            float o = a + action[(size_t)row * ADIM + k];
            o = fminf(fmaxf(o, -1.0f), 1.0f);
            out[(size_t)row * ADIM + k] = o;
        }
        __syncthreads();
    }
}

// ---------------- launch ----------------
extern "C" void kernel_launch(void* const* d_in, const int* in_sizes, int n_in,
                              void* d_out, int out_size) {
    (void)in_sizes; (void)n_in; (void)out_size;
    const float* state  = (const float*)d_in[0];
    const float* action = (const float*)d_in[1];
    const float* W1     = (const float*)d_in[2];
    const float* b1     = (const float*)d_in[3];
    const float* W2     = (const float*)d_in[4];
    const float* b2     = (const float*)d_in[5];
    const float* W3     = (const float*)d_in[6];
    const float* b3     = (const float*)d_in[7];
    float* out = (float*)d_out;

    cudaFuncSetAttribute(k_fused, cudaFuncAttributeMaxDynamicSharedMemorySize,
                         5120 + 2 * KCH * SBST * 2);

    k_pack_input<<<(BATCH * (DPAD / 8) + 255) / 256, 256>>>(state, action);
    k_pack_w1<<<(DPAD * NPAD + 255) / 256, 256>>>(W1);
    k_prep<<<H1 + 1, 32>>>(W2, b2, b3);

    k_fused<<<BATCH / 32, 256, 5120 + 2 * KCH * SBST * 2>>>(b1, action, out);

    k_snn<<<128, 320>>>(action, W2, b2, W3, b3, out);
}

// round 6
// speedup vs baseline: 2.0002x; 2.0002x over previous
#include <cuda_runtime.h>
#include <cuda_bf16.h>
#include <mma.h>
#include <math.h>

using namespace nvcuda;

#define BATCH 8192
#define SDIM  376
#define ADIM  17
#define DIN   393
#define DPAD  416           // padded K: 13 chunks of 32
#define KCH   32
#define NCHK  13
#define H1    400
#define NPAD  448           // padded N (4 col-sets of 112 = 7 frags)
#define SBST  456           // B smem stride (odd multiple of 8 -> conflict-free)
#define SAST  424           // full-K A smem stride (53 x 16B, odd -> conflict-free)
#define H2    300
#define TSTEPS 32

#define CAPC  24
#define CAP1  96
#define CAP2  96

// smem layout (dynamic): [A 32*424*2 = 27136][B0 29184][B1 29184] = 85504
#define SM_A    0
#define SM_B0   27136
#define SM_B1   (27136 + 29184)
#define SM_DYN  (27136 + 2 * 29184)

// ---------------- static device scratch ----------------
__device__ __align__(16) __nv_bfloat16 g_W1p[(size_t)DPAD * NPAD];
__device__ __align__(16) unsigned      g_S1[(size_t)BATCH * H1];   // slow rows only
__device__ float g_c[H1];          // c_i = max_j W2[i,j]
__device__ float g_b2max;
__device__ float g_const[ADIM];    // 0.05*tanh(vmax(b3_k))
__device__ int   g_nslow;
__device__ int   g_slowlist[BATCH];

// ---------------- cp.async helpers ----------------
__device__ __forceinline__ void cp16(void* dst, const void* src) {
    unsigned d = (unsigned)__cvta_generic_to_shared(dst);
    asm volatile("cp.async.cg.shared.global [%0], [%1], 16;\n" :: "r"(d), "l"(src));
}
__device__ __forceinline__ void cp_commit() {
    asm volatile("cp.async.commit_group;\n");
}
template<int N> __device__ __forceinline__ void cp_wait() {
    asm volatile("cp.async.wait_group %0;\n" :: "n"(N));
}

// ---------------- K0b: pack W1 -> [416][448] bf16, zero pad ----------------
__global__ void k_pack_w1(const float* __restrict__ W1) {
    int idx = blockIdx.x * blockDim.x + threadIdx.x;
    if (idx >= DPAD * NPAD) return;
    int r = idx / NPAD;
    int c = idx - r * NPAD;
    float f = (r < DIN && c < H1) ? W1[(size_t)r * H1 + c] : 0.0f;
    g_W1p[idx] = __float2bfloat16(f);
}

// ---------------- K_prep: c_i, b2max, const_k, reset list ----------------
__global__ void k_prep(const float* __restrict__ W2,
                       const float* __restrict__ b2,
                       const float* __restrict__ b3) {
    int bid  = blockIdx.x;
    int lane = threadIdx.x;
    if (bid < H1) {
        float m = -3.4e38f;
        for (int j = lane; j < H2; j += 32)
            m = fmaxf(m, W2[(size_t)bid * H2 + j]);
#pragma unroll
        for (int o = 16; o; o >>= 1) m = fmaxf(m, __shfl_xor_sync(0xffffffffu, m, o));
        if (lane == 0) g_c[bid] = m;
    } else {
        float m = -3.4e38f;
        for (int j = lane; j < H2; j += 32) m = fmaxf(m, b2[j]);
#pragma unroll
        for (int o = 16; o; o >>= 1) m = fmaxf(m, __shfl_xor_sync(0xffffffffu, m, o));
        if (lane == 0) g_b2max = m;
        if (lane == 20) g_nslow = 0;
        if (lane < ADIM) {
            float b = b3[lane];
            float vmax = (b > 0.0f) ? b : 0.5f * b;   // monotone v3 = b3*(1-2^-t)
            g_const[lane] = 0.05f * tanhf(vmax);
        }
    }
}

// ---------------- K1: fused [pack A]+GEMM+LIF1+bound-check+fast output -----
// tile: 32 rows x 448 cols. 8 warps: rg=w>>2 (16 rows), cs=w&3 (112 cols).
// A loaded fp32 from state/action, converted to bf16 smem once (full K).
__global__ __launch_bounds__(256, 2) void k_fused(const float* __restrict__ state,
                                                  const float* __restrict__ action,
                                                  const float* __restrict__ b1,
                                                  float* __restrict__ out) {
    extern __shared__ __align__(16) unsigned char sm[];
    __nv_bfloat16* sA  = reinterpret_cast<__nv_bfloat16*>(sm + SM_A);
    __nv_bfloat16* sB0 = reinterpret_cast<__nv_bfloat16*>(sm + SM_B0);
    __nv_bfloat16* sB1 = reinterpret_cast<__nv_bfloat16*>(sm + SM_B1);
    float*    stage   = reinterpret_cast<float*>(sm);     // epilogue overlay
    unsigned* stage_u = reinterpret_cast<unsigned*>(sm);

    __shared__ float s_c[H1];
    __shared__ float s_b1[H1];
    __shared__ float s_const[ADIM];
    __shared__ float s_b2max;

    const int tid  = threadIdx.x;
    const int lane = tid & 31;
    const int w    = tid >> 5;
    const int rg   = w >> 2;
    const int cs   = w & 3;
    const int m0   = blockIdx.x * 32;

    auto load_B = [&](int c, __nv_bfloat16* dst) {
        // 32 k-rows x 448 cols -> 1792 cp16 (7 per thread)
#pragma unroll
        for (int rep = 0; rep < 7; rep++) {
            int t2 = tid + rep * 256;
            int r = t2 / 56, p = t2 - r * 56;
            cp16(dst + r * SBST + 8 * p,
                 &g_W1p[(size_t)(c * KCH + r) * NPAD + 8 * p]);
        }
    };

    // kick off first B chunk immediately (overlaps A conversion)
    load_B(0, sB0);
    cp_commit();

    // constants
    for (int i = tid; i < H1; i += 256) { s_c[i] = g_c[i]; s_b1[i] = b1[i]; }
    if (tid < ADIM) s_const[tid] = g_const[tid];
    if (tid == 32)  s_b2max = g_b2max;

    // A: load fp32 state/action, convert to bf16 smem (32 x 416, stride 424)
    for (int idx = tid; idx < 32 * SDIM; idx += 256) {
        int r = idx / SDIM, c = idx - r * SDIM;
        sA[r * SAST + c] = __float2bfloat16(state[(size_t)(m0 + r) * SDIM + c]);
    }
    for (int idx = tid; idx < 32 * ADIM; idx += 256) {
        int r = idx / ADIM, c = idx - r * ADIM;
        sA[r * SAST + SDIM + c] = __float2bfloat16(action[(size_t)(m0 + r) * ADIM + c]);
    }
    for (int idx = tid; idx < 32 * (DPAD - DIN); idx += 256) {
        int r = idx / (DPAD - DIN), c = idx - r * (DPAD - DIN);
        sA[r * SAST + DIN + c] = __float2bfloat16(0.0f);
    }

    wmma::fragment<wmma::accumulator, 16, 16, 16, float> acc[7];
#pragma unroll
    for (int f = 0; f < 7; f++) wmma::fill_fragment(acc[f], 0.0f);

    for (int c = 0; c < NCHK; c++) {
        __nv_bfloat16* cur = (c & 1) ? sB1 : sB0;
        __nv_bfloat16* nxt = (c & 1) ? sB0 : sB1;
        if (c + 1 < NCHK) {
            load_B(c + 1, nxt);
            cp_commit();
            cp_wait<1>();
        } else {
            cp_wait<0>();
        }
        __syncthreads();       // also covers A-fill completion on c==0

#pragma unroll
        for (int ks = 0; ks < 2; ks++) {
            wmma::fragment<wmma::matrix_a, 16, 16, 16, __nv_bfloat16, wmma::row_major> afrag;
            wmma::load_matrix_sync(afrag,
                sA + (rg * 16) * SAST + c * KCH + ks * 16, SAST);
#pragma unroll
            for (int f = 0; f < 7; f++) {
                wmma::fragment<wmma::matrix_b, 16, 16, 16, __nv_bfloat16, wmma::row_major> bfrag;
                wmma::load_matrix_sync(bfrag,
                    cur + (ks * 16) * SBST + cs * 112 + f * 16, SBST);
                wmma::mma_sync(acc[f], afrag, bfrag, acc[f]);
            }
        }
        __syncthreads();
    }

    // ---- epilogue: stage fp32 (overlay), LIF -> word in-place, row check ----
#pragma unroll
    for (int f = 0; f < 7; f++)
        wmma::store_matrix_sync(&stage[(rg * 16) * SBST + cs * 112 + f * 16],
                                acc[f], SBST, wmma::mem_row_major);
    __syncthreads();

    for (int idx = tid; idx < 32 * H1; idx += 256) {
        int r = idx / H1;
        int c = idx - r * H1;
        float x = stage[r * SBST + c] + s_b1[c];
        unsigned word = 0u;
        if (x >= 0.999999f) {              // v_t < x always: x<1 can't spike
            float v = 0.0f;
#pragma unroll
            for (int t = 0; t < TSTEPS; t++) {
                v = fmaf(x - v, 0.5f, v);
                if (v >= 1.0f) { word |= (1u << t); v = 0.0f; }
            }
        }
        stage_u[r * SBST + c] = word;
    }
    __syncthreads();

    // per-row check: warp w handles rows w*4 .. w*4+3
#pragma unroll
    for (int rr = 0; rr < 4; rr++) {
        int r = w * 4 + rr;
        int grow = m0 + r;
        float accu = 0.0f;                 // lane = timestep
        for (int ch = 0; ch < 13; ch++) {
            int i = ch * 32 + lane;
            unsigned word = (i < H1) ? stage_u[r * SBST + i] : 0u;
            unsigned bal = __ballot_sync(0xffffffffu, word != 0u);
            while (bal) {
                int b = __ffs(bal) - 1;
                bal &= bal - 1;
                unsigned wb = __shfl_sync(0xffffffffu, word, b);
                float ci = s_c[ch * 32 + b];
                if ((wb >> lane) & 1u) accu += ci;
            }
        }
        float m = accu;
#pragma unroll
        for (int o = 16; o; o >>= 1) m = fmaxf(m, __shfl_xor_sync(0xffffffffu, m, o));
        int slow = (s_b2max + m >= 1.0f);

        if (!slow) {
            if (lane < ADIM) {
                float o = s_const[lane] + action[(size_t)grow * ADIM + lane];
                out[(size_t)grow * ADIM + lane] = fminf(fmaxf(o, -1.0f), 1.0f);
            }
        } else {
            for (int ch = 0; ch < 13; ch++) {
                int i = ch * 32 + lane;
                if (i < H1)
                    g_S1[(size_t)grow * H1 + i] = stage_u[r * SBST + i];
            }
            if (lane == 0) {
                int s = atomicAdd(&g_nslow, 1);
                g_slowlist[s] = grow;
            }
        }
    }
}

// ---------------- K2: exact slow path over compact list (2048-way) --------
__global__ __launch_bounds__(320) void k_snn(const float* __restrict__ action,
                                             const float* __restrict__ W2,
                                             const float* __restrict__ b2,
                                             const float* __restrict__ W3,
                                             const float* __restrict__ b3,
                                             float* __restrict__ out) {
    __shared__ float          s_w2[CAPC * H2];
    __shared__ unsigned       s_mask1[H1];
    __shared__ unsigned short s_fire[H1];
    __shared__ unsigned short s_list1[TSTEPS][CAP1];
    __shared__ int            s_cnt1[TSTEPS];
    __shared__ unsigned       s_mask2[H2];
    __shared__ unsigned short s_list2[TSTEPS][CAP2];
    __shared__ int            s_cnt2[TSTEPS];
    __shared__ int            s_nf;

    int tid  = threadIdx.x;
    int lane = tid & 31;
    int w    = tid >> 5;
    unsigned lmask = (1u << lane) - 1u;
    int nslow = g_nslow;

    for (int s = blockIdx.x; s < nslow; s += gridDim.x) {
        int row = g_slowlist[s];

        for (int i = tid; i < H1; i += 320)
            s_mask1[i] = g_S1[(size_t)row * H1 + i];
        __syncthreads();

        if (w == 0) {
            int nf = 0;
            for (int c = 0; c * 32 < H1; c++) {
                int i = c * 32 + lane;
                unsigned m = (i < H1) ? s_mask1[i] : 0u;
                int pred = (m != 0u);
                unsigned bal = __ballot_sync(0xffffffffu, pred);
                int pos = nf + __popc(bal & lmask);
                if (pred) s_fire[pos] = (unsigned short)i;
                nf += __popc(bal);
            }
            if (lane == 0) s_nf = nf;
        }
        __syncthreads();
        int nf = s_nf;
        int ncache = nf < CAPC ? nf : CAPC;

        for (int idx = tid; idx < ncache * H2; idx += 320) {
            int q = idx / H2;
            int j = idx - q * H2;
            s_w2[q * H2 + j] = W2[(size_t)s_fire[q] * H2 + j];
        }

        for (int t = w; t < TSTEPS; t += 10) {
            int cnt = 0;
            for (int c = 0; c * 32 < nf; c++) {
                int qi = c * 32 + lane;
                int pred = 0; unsigned short entry = 0;
                if (qi < nf) {
                    int i = s_fire[qi];
                    if ((s_mask1[i] >> t) & 1u) {
                        pred = 1;
                        entry = (qi < CAPC) ? (unsigned short)qi
                                            : (unsigned short)(256 + i);
                    }
                }
                unsigned bal = __ballot_sync(0xffffffffu, pred);
                int pos = cnt + __popc(bal & lmask);
                if (pred && pos < CAP1) s_list1[t][pos] = entry;
                cnt += __popc(bal);
            }
            s_cnt1[t] = cnt < CAP1 ? cnt : CAP1;
        }
        __syncthreads();

        if (tid < H2) {
            int j = tid;
            float b2j = b2[j];
            float v2 = 0.0f;
            unsigned mask2 = 0u;
            for (int t = 0; t < TSTEPS; t++) {
                float x2 = b2j;
                int n = s_cnt1[t];
                for (int q = 0; q < n; q++) {
                    int e = s_list1[t][q];
                    float wv = (e < CAPC) ? s_w2[e * H2 + j]
                                          : W2[(size_t)(e - 256) * H2 + j];
                    x2 += wv;
                }
                v2 += (x2 - v2) * 0.5f;
                if (v2 >= 1.0f) { mask2 |= (1u << t); v2 = 0.0f; }
            }
            s_mask2[j] = mask2;
        }
        __syncthreads();

        for (int t = w; t < TSTEPS; t += 10) {
            int cnt = 0;
            for (int c = 0; c * 32 < H2; c++) {
                int j = c * 32 + lane;
                int pred = 0;
                if (j < H2) pred = (int)((s_mask2[j] >> t) & 1u);
                unsigned bal = __ballot_sync(0xffffffffu, pred);
                int pos = cnt + __popc(bal & lmask);
                if (pred && pos < CAP2) s_list2[t][pos] = (unsigned short)j;
                cnt += __popc(bal);
            }
            s_cnt2[t] = cnt < CAP2 ? cnt : CAP2;
        }
        __syncthreads();

        if (tid < ADIM) {
            int k = tid;
            float b3k = b3[k];
            float v3 = 0.0f, vmax = -3.4e38f;
            for (int t = 0; t < TSTEPS; t++) {
                float x3 = b3k;
                int n = s_cnt2[t];
                for (int q = 0; q < n; q++) {
                    int j = s_list2[t][q];
                    x3 += W3[j * ADIM + k];
                }
                v3 += (x3 - v3) * 0.5f;
                vmax = fmaxf(vmax, v3);
            }
            float a = 0.05f * tanhf(vmax);
            float o = a + action[(size_t)row * ADIM + k];
            o = fminf(fmaxf(o, -1.0f), 1.0f);
            out[(size_t)row * ADIM + k] = o;
        }
        __syncthreads();
    }
}

// ---------------- launch ----------------
extern "C" void kernel_launch(void* const* d_in, const int* in_sizes, int n_in,
                              void* d_out, int out_size) {
    (void)in_sizes; (void)n_in; (void)out_size;
    const float* state  = (const float*)d_in[0];
    const float* action = (const float*)d_in[1];
    const float* W1     = (const float*)d_in[2];
    const float* b1     = (const float*)d_in[3];
    const float* W2     = (const float*)d_in[4];
    const float* b2     = (const float*)d_in[5];
    const float* W3     = (const float*)d_in[6];
    const float* b3     = (const float*)d_in[7];
    float* out = (float*)d_out;

    cudaFuncSetAttribute(k_fused, cudaFuncAttributeMaxDynamicSharedMemorySize,
                         SM_DYN);

    k_pack_w1<<<(DPAD * NPAD + 255) / 256, 256>>>(W1);
    k_prep<<<H1 + 1, 32>>>(W2, b2, b3);

    k_fused<<<BATCH / 32, 256, SM_DYN>>>(state, action, b1, out);

    k_snn<<<2048, 320>>>(action, W2, b2, W3, b3, out);
}

// round 7
// speedup vs baseline: 2.7345x; 1.3671x over previous
#include <cuda_runtime.h>
#include <cuda_bf16.h>
#include <mma.h>
#include <math.h>

using namespace nvcuda;

#define BATCH 8192
#define SDIM  376
#define ADIM  17
#define DIN   393
#define DPAD  416           // padded K: 13 chunks of 32
#define KCH   32
#define NCHK  13
#define H1    400
#define NPAD  448           // padded N (4 col-sets of 112 = 7 frags)
#define SBST  456           // B smem stride (odd multiple of 8 -> conflict-free)
#define SAST  424           // full-K A smem stride (53 x 16B, odd -> conflict-free)
#define H2    300
#define TSTEPS 32

#define CAPC  24
#define CAP1  96
#define CAP2  96

// smem layout (dynamic): [A 32*424*2 = 27136][B0 29184][B1 29184] = 85504
#define SM_A    0
#define SM_B0   27136
#define SM_B1   (27136 + 29184)
#define SM_DYN  (27136 + 2 * 29184)

// ---------------- static device scratch ----------------
__device__ __align__(16) __nv_bfloat16 g_W1p[(size_t)DPAD * NPAD];
__device__ __align__(16) unsigned      g_S1[(size_t)BATCH * H1];   // slow rows only
__device__ float g_c[H1];          // c_i = max_j W2[i,j]
__device__ float g_b2max;
__device__ float g_const[ADIM];    // 0.05*tanh(vmax(b3_k))
__device__ int   g_nslow;
__device__ int   g_slowlist[BATCH];

// ---------------- cp.async helpers ----------------
__device__ __forceinline__ void cp16(void* dst, const void* src) {
    unsigned d = (unsigned)__cvta_generic_to_shared(dst);
    asm volatile("cp.async.cg.shared.global [%0], [%1], 16;\n" :: "r"(d), "l"(src));
}
__device__ __forceinline__ void cp_commit() {
    asm volatile("cp.async.commit_group;\n");
}
template<int N> __device__ __forceinline__ void cp_wait() {
    asm volatile("cp.async.wait_group %0;\n" :: "n"(N));
}

// ---------------- K0b: pack W1 -> [416][448] bf16, zero pad ----------------
__global__ void k_pack_w1(const float* __restrict__ W1) {
    int idx = blockIdx.x * blockDim.x + threadIdx.x;
    if (idx >= DPAD * NPAD) return;
    int r = idx / NPAD;
    int c = idx - r * NPAD;
    float f = (r < DIN && c < H1) ? W1[(size_t)r * H1 + c] : 0.0f;
    g_W1p[idx] = __float2bfloat16(f);
}

// ---------------- K_prep: c_i, b2max, const_k, reset list ----------------
__global__ void k_prep(const float* __restrict__ W2,
                       const float* __restrict__ b2,
                       const float* __restrict__ b3) {
    int bid  = blockIdx.x;
    int lane = threadIdx.x;
    if (bid < H1) {
        float m = -3.4e38f;
        for (int j = lane; j < H2; j += 32)
            m = fmaxf(m, W2[(size_t)bid * H2 + j]);
#pragma unroll
        for (int o = 16; o; o >>= 1) m = fmaxf(m, __shfl_xor_sync(0xffffffffu, m, o));
        if (lane == 0) g_c[bid] = m;
    } else {
        float m = -3.4e38f;
        for (int j = lane; j < H2; j += 32) m = fmaxf(m, b2[j]);
#pragma unroll
        for (int o = 16; o; o >>= 1) m = fmaxf(m, __shfl_xor_sync(0xffffffffu, m, o));
        if (lane == 0) g_b2max = m;
        if (lane == 20) g_nslow = 0;
        if (lane < ADIM) {
            float b = b3[lane];
            float vmax = (b > 0.0f) ? b : 0.5f * b;   // monotone v3 = b3*(1-2^-t)
            g_const[lane] = 0.05f * tanhf(vmax);
        }
    }
}

// ---------------- K1: fused [pack A]+GEMM+LIF1+bound-check+fast output -----
// tile: 32 rows x 448 cols. 8 warps: rg=w>>2 (16 rows), cs=w&3 (112 cols).
__global__ __launch_bounds__(256, 2) void k_fused(const float* __restrict__ state,
                                                  const float* __restrict__ action,
                                                  const float* __restrict__ b1,
                                                  float* __restrict__ out) {
    extern __shared__ __align__(16) unsigned char sm[];
    __nv_bfloat16* sA  = reinterpret_cast<__nv_bfloat16*>(sm + SM_A);
    __nv_bfloat16* sB0 = reinterpret_cast<__nv_bfloat16*>(sm + SM_B0);
    __nv_bfloat16* sB1 = reinterpret_cast<__nv_bfloat16*>(sm + SM_B1);
    float*    stage   = reinterpret_cast<float*>(sm);     // epilogue overlay
    unsigned* stage_u = reinterpret_cast<unsigned*>(sm);

    __shared__ float s_c[H1];
    __shared__ float s_b1[H1];
    __shared__ float s_const[ADIM];
    __shared__ float s_b2max;

    const int tid  = threadIdx.x;
    const int lane = tid & 31;
    const int w    = tid >> 5;
    const int rg   = w >> 2;
    const int cs   = w & 3;
    const int m0   = blockIdx.x * 32;

    auto load_B = [&](int c, __nv_bfloat16* dst) {
#pragma unroll
        for (int rep = 0; rep < 7; rep++) {
            int t2 = tid + rep * 256;
            int r = t2 / 56, p = t2 - r * 56;
            cp16(dst + r * SBST + 8 * p,
                 &g_W1p[(size_t)(c * KCH + r) * NPAD + 8 * p]);
        }
    };

    // kick off first B chunk immediately (overlaps A conversion)
    load_B(0, sB0);
    cp_commit();

    // constants
    for (int i = tid; i < H1; i += 256) { s_c[i] = g_c[i]; s_b1[i] = b1[i]; }
    if (tid < ADIM) s_const[tid] = g_const[tid];
    if (tid == 32)  s_b2max = g_b2max;

    // A: load fp32 state/action, convert to bf16 smem (32 x 416, stride 424)
    for (int idx = tid; idx < 32 * SDIM; idx += 256) {
        int r = idx / SDIM, c = idx - r * SDIM;
        sA[r * SAST + c] = __float2bfloat16(state[(size_t)(m0 + r) * SDIM + c]);
    }
    for (int idx = tid; idx < 32 * ADIM; idx += 256) {
        int r = idx / ADIM, c = idx - r * ADIM;
        sA[r * SAST + SDIM + c] = __float2bfloat16(action[(size_t)(m0 + r) * ADIM + c]);
    }
    for (int idx = tid; idx < 32 * (DPAD - DIN); idx += 256) {
        int r = idx / (DPAD - DIN), c = idx - r * (DPAD - DIN);
        sA[r * SAST + DIN + c] = __float2bfloat16(0.0f);
    }

    wmma::fragment<wmma::accumulator, 16, 16, 16, float> acc[7];
#pragma unroll
    for (int f = 0; f < 7; f++) wmma::fill_fragment(acc[f], 0.0f);

    for (int c = 0; c < NCHK; c++) {
        __nv_bfloat16* cur = (c & 1) ? sB1 : sB0;
        __nv_bfloat16* nxt = (c & 1) ? sB0 : sB1;
        if (c + 1 < NCHK) {
            load_B(c + 1, nxt);
            cp_commit();
            cp_wait<1>();
        } else {
            cp_wait<0>();
        }
        __syncthreads();       // also covers A-fill completion on c==0

#pragma unroll
        for (int ks = 0; ks < 2; ks++) {
            wmma::fragment<wmma::matrix_a, 16, 16, 16, __nv_bfloat16, wmma::row_major> afrag;
            wmma::load_matrix_sync(afrag,
                sA + (rg * 16) * SAST + c * KCH + ks * 16, SAST);
#pragma unroll
            for (int f = 0; f < 7; f++) {
                wmma::fragment<wmma::matrix_b, 16, 16, 16, __nv_bfloat16, wmma::row_major> bfrag;
                wmma::load_matrix_sync(bfrag,
                    cur + (ks * 16) * SBST + cs * 112 + f * 16, SBST);
                wmma::mma_sync(acc[f], afrag, bfrag, acc[f]);
            }
        }
        __syncthreads();
    }

    // ---- epilogue: stage fp32 (overlay), LIF -> word in-place, row check ----
#pragma unroll
    for (int f = 0; f < 7; f++)
        wmma::store_matrix_sync(&stage[(rg * 16) * SBST + cs * 112 + f * 16],
                                acc[f], SBST, wmma::mem_row_major);
    __syncthreads();

    for (int idx = tid; idx < 32 * H1; idx += 256) {
        int r = idx / H1;
        int c = idx - r * H1;
        float x = stage[r * SBST + c] + s_b1[c];
        unsigned word = 0u;
        if (x >= 0.999999f) {              // v_t < x always: x<1 can't spike
            float v = 0.0f;
#pragma unroll
            for (int t = 0; t < TSTEPS; t++) {
                v = fmaf(x - v, 0.5f, v);
                if (v >= 1.0f) { word |= (1u << t); v = 0.0f; }
            }
        }
        stage_u[r * SBST + c] = word;
    }
    __syncthreads();

    // per-row check: warp w handles rows w*4 .. w*4+3
#pragma unroll
    for (int rr = 0; rr < 4; rr++) {
        int r = w * 4 + rr;
        int grow = m0 + r;
        float accu = 0.0f;                 // lane = timestep
        for (int ch = 0; ch < 13; ch++) {
            int i = ch * 32 + lane;
            unsigned word = (i < H1) ? stage_u[r * SBST + i] : 0u;
            unsigned bal = __ballot_sync(0xffffffffu, word != 0u);
            while (bal) {
                int b = __ffs(bal) - 1;
                bal &= bal - 1;
                unsigned wb = __shfl_sync(0xffffffffu, word, b);
                float ci = s_c[ch * 32 + b];
                if ((wb >> lane) & 1u) accu += ci;
            }
        }
        // TIGHT bound: run the LIF-2 recurrence on per-timestep upper bounds.
        // x2_j(t) <= u(t) = b2max + sum_{i in fire(t)} c_i, and while no spike
        // has occurred v2_j(t) = (v2_j(t-1) + x2_j(t))/2 <= vb(t). If vb(t) < 1
        // for all t, layer 2 provably never spikes.
        float u = s_b2max + accu;          // this lane's timestep bound
        float vb = 0.0f, vbmax = -3.4e38f;
#pragma unroll
        for (int t = 0; t < TSTEPS; t++) {
            float ut = __shfl_sync(0xffffffffu, u, t);
            vb = 0.5f * (vb + ut);
            vbmax = fmaxf(vbmax, vb);
        }
        int slow = (vbmax >= 1.0f);

        if (!slow) {
            if (lane < ADIM) {
                float o = s_const[lane] + action[(size_t)grow * ADIM + lane];
                out[(size_t)grow * ADIM + lane] = fminf(fmaxf(o, -1.0f), 1.0f);
            }
        } else {
            for (int ch = 0; ch < 13; ch++) {
                int i = ch * 32 + lane;
                if (i < H1)
                    g_S1[(size_t)grow * H1 + i] = stage_u[r * SBST + i];
            }
            if (lane == 0) {
                int s = atomicAdd(&g_nslow, 1);
                g_slowlist[s] = grow;
            }
        }
    }
}

// ---------------- K2: exact slow path over compact list (2048-way) --------
__global__ __launch_bounds__(320) void k_snn(const float* __restrict__ action,
                                             const float* __restrict__ W2,
                                             const float* __restrict__ b2,
                                             const float* __restrict__ W3,
                                             const float* __restrict__ b3,
                                             float* __restrict__ out) {
    __shared__ float          s_w2[CAPC * H2];
    __shared__ unsigned       s_mask1[H1];
    __shared__ unsigned short s_fire[H1];
    __shared__ unsigned short s_list1[TSTEPS][CAP1];
    __shared__ int            s_cnt1[TSTEPS];
    __shared__ unsigned       s_mask2[H2];
    __shared__ unsigned short s_list2[TSTEPS][CAP2];
    __shared__ int            s_cnt2[TSTEPS];
    __shared__ int            s_nf;

    int tid  = threadIdx.x;
    int lane = tid & 31;
    int w    = tid >> 5;
    unsigned lmask = (1u << lane) - 1u;
    int nslow = g_nslow;

    for (int s = blockIdx.x; s < nslow; s += gridDim.x) {
        int row = g_slowlist[s];

        for (int i = tid; i < H1; i += 320)
            s_mask1[i] = g_S1[(size_t)row * H1 + i];
        __syncthreads();

        if (w == 0) {
            int nf = 0;
            for (int c = 0; c * 32 < H1; c++) {
                int i = c * 32 + lane;
                unsigned m = (i < H1) ? s_mask1[i] : 0u;
                int pred = (m != 0u);
                unsigned bal = __ballot_sync(0xffffffffu, pred);
                int pos = nf + __popc(bal & lmask);
                if (pred) s_fire[pos] = (unsigned short)i;
                nf += __popc(bal);
            }
            if (lane == 0) s_nf = nf;
        }
        __syncthreads();
        int nf = s_nf;
        int ncache = nf < CAPC ? nf : CAPC;

        for (int idx = tid; idx < ncache * H2; idx += 320) {
            int q = idx / H2;
            int j = idx - q * H2;
            s_w2[q * H2 + j] = W2[(size_t)s_fire[q] * H2 + j];
        }

        for (int t = w; t < TSTEPS; t += 10) {
            int cnt = 0;
            for (int c = 0; c * 32 < nf; c++) {
                int qi = c * 32 + lane;
                int pred = 0; unsigned short entry = 0;
                if (qi < nf) {
                    int i = s_fire[qi];
                    if ((s_mask1[i] >> t) & 1u) {
                        pred = 1;
                        entry = (qi < CAPC) ? (unsigned short)qi
                                            : (unsigned short)(256 + i);
                    }
                }
                unsigned bal = __ballot_sync(0xffffffffu, pred);
                int pos = cnt + __popc(bal & lmask);
                if (pred && pos < CAP1) s_list1[t][pos] = entry;
                cnt += __popc(bal);
            }
            s_cnt1[t] = cnt < CAP1 ? cnt : CAP1;
        }
        __syncthreads();

        if (tid < H2) {
            int j = tid;
            float b2j = b2[j];
            float v2 = 0.0f;
            unsigned mask2 = 0u;
            for (int t = 0; t < TSTEPS; t++) {
                float x2 = b2j;
                int n = s_cnt1[t];
                for (int q = 0; q < n; q++) {
                    int e = s_list1[t][q];
                    float wv = (e < CAPC) ? s_w2[e * H2 + j]
                                          : W2[(size_t)(e - 256) * H2 + j];
                    x2 += wv;
                }
                v2 += (x2 - v2) * 0.5f;
                if (v2 >= 1.0f) { mask2 |= (1u << t); v2 = 0.0f; }
            }
            s_mask2[j] = mask2;
        }
        __syncthreads();

        for (int t = w; t < TSTEPS; t += 10) {
            int cnt = 0;
            for (int c = 0; c * 32 < H2; c++) {
                int j = c * 32 + lane;
                int pred = 0;
                if (j < H2) pred = (int)((s_mask2[j] >> t) & 1u);
                unsigned bal = __ballot_sync(0xffffffffu, pred);
                int pos = cnt + __popc(bal & lmask);
                if (pred && pos < CAP2) s_list2[t][pos] = (unsigned short)j;
                cnt += __popc(bal);
            }
            s_cnt2[t] = cnt < CAP2 ? cnt : CAP2;
        }
        __syncthreads();

        if (tid < ADIM) {
            int k = tid;
            float b3k = b3[k];
            float v3 = 0.0f, vmax = -3.4e38f;
            for (int t = 0; t < TSTEPS; t++) {
                float x3 = b3k;
                int n = s_cnt2[t];
                for (int q = 0; q < n; q++) {
                    int j = s_list2[t][q];
                    x3 += W3[j * ADIM + k];
                }
                v3 += (x3 - v3) * 0.5f;
                vmax = fmaxf(vmax, v3);
            }
            float a = 0.05f * tanhf(vmax);
            float o = a + action[(size_t)row * ADIM + k];
            o = fminf(fmaxf(o, -1.0f), 1.0f);
            out[(size_t)row * ADIM + k] = o;
        }
        __syncthreads();
    }
}

// ---------------- launch ----------------
extern "C" void kernel_launch(void* const* d_in, const int* in_sizes, int n_in,
                              void* d_out, int out_size) {
    (void)in_sizes; (void)n_in; (void)out_size;
    const float* state  = (const float*)d_in[0];
    const float* action = (const float*)d_in[1];
    const float* W1     = (const float*)d_in[2];
    const float* b1     = (const float*)d_in[3];
    const float* W2     = (const float*)d_in[4];
    const float* b2     = (const float*)d_in[5];
    const float* W3     = (const float*)d_in[6];
    const float* b3     = (const float*)d_in[7];
    float* out = (float*)d_out;

    cudaFuncSetAttribute(k_fused, cudaFuncAttributeMaxDynamicSharedMemorySize,
                         SM_DYN);

    k_pack_w1<<<(DPAD * NPAD + 255) / 256, 256>>>(W1);
    k_prep<<<H1 + 1, 32>>>(W2, b2, b3);

    k_fused<<<BATCH / 32, 256, SM_DYN>>>(state, action, b1, out);

    k_snn<<<2048, 320>>>(action, W2, b2, W3, b3, out);
}

// round 8
// speedup vs baseline: 3.3107x; 1.2107x over previous
#include <cuda_runtime.h>
#include <cuda_bf16.h>
#include <mma.h>
#include <math.h>

using namespace nvcuda;

#define BATCH 8192
#define SDIM  376
#define ADIM  17
#define DIN   393
#define DPAD  416           // padded K: 13 chunks of 32
#define KCH   32
#define NCHK  13
#define H1    400
#define NPAD  448           // padded N (4 col-sets of 112 = 7 frags)
#define SBST  456           // B smem stride (odd multiple of 8 -> conflict-free)
#define SAST  424           // full-K A smem stride (53 x 16B, odd -> conflict-free)
#define H2    300
#define TSTEPS 32

#define CAP2  96

// smem layout (dynamic): [A 32*424*2 = 27136][B0 29184][B1 29184] = 85504
#define SM_A    0
#define SM_B0   27136
#define SM_B1   (27136 + 29184)
#define SM_DYN  (27136 + 2 * 29184)

// ---------------- static device scratch ----------------
__device__ __align__(16) __nv_bfloat16 g_W1p[(size_t)DPAD * NPAD];
__device__ __align__(16) unsigned      g_S1[(size_t)BATCH * H1];   // slow rows only
__device__ float g_c[H1];          // c_i = max_j W2[i,j]
__device__ float g_b2max;
__device__ float g_const[ADIM];    // 0.05*tanh(vmax(b3_k))
__device__ int   g_nslow;
__device__ int   g_slowlist[BATCH];

// ---------------- cp.async helpers ----------------
__device__ __forceinline__ void cp16(void* dst, const void* src) {
    unsigned d = (unsigned)__cvta_generic_to_shared(dst);
    asm volatile("cp.async.cg.shared.global [%0], [%1], 16;\n" :: "r"(d), "l"(src));
}
__device__ __forceinline__ void cp_commit() {
    asm volatile("cp.async.commit_group;\n");
}
template<int N> __device__ __forceinline__ void cp_wait() {
    asm volatile("cp.async.wait_group %0;\n" :: "n"(N));
}

// ---------------- K0b: pack W1 -> [416][448] bf16, zero pad ----------------
__global__ void k_pack_w1(const float* __restrict__ W1) {
    int idx = blockIdx.x * blockDim.x + threadIdx.x;
    if (idx >= DPAD * NPAD) return;
    int r = idx / NPAD;
    int c = idx - r * NPAD;
    float f = (r < DIN && c < H1) ? W1[(size_t)r * H1 + c] : 0.0f;
    g_W1p[idx] = __float2bfloat16(f);
}

// ---------------- K_prep: c_i, b2max, const_k, reset list ----------------
__global__ void k_prep(const float* __restrict__ W2,
                       const float* __restrict__ b2,
                       const float* __restrict__ b3) {
    int bid  = blockIdx.x;
    int lane = threadIdx.x;
    if (bid < H1) {
        float m = -3.4e38f;
        for (int j = lane; j < H2; j += 32)
            m = fmaxf(m, W2[(size_t)bid * H2 + j]);
#pragma unroll
        for (int o = 16; o; o >>= 1) m = fmaxf(m, __shfl_xor_sync(0xffffffffu, m, o));
        if (lane == 0) g_c[bid] = m;
    } else {
        float m = -3.4e38f;
        for (int j = lane; j < H2; j += 32) m = fmaxf(m, b2[j]);
#pragma unroll
        for (int o = 16; o; o >>= 1) m = fmaxf(m, __shfl_xor_sync(0xffffffffu, m, o));
        if (lane == 0) g_b2max = m;
        if (lane == 20) g_nslow = 0;
        if (lane < ADIM) {
            float b = b3[lane];
            float vmax = (b > 0.0f) ? b : 0.5f * b;   // monotone v3 = b3*(1-2^-t)
            g_const[lane] = 0.05f * tanhf(vmax);
        }
    }
}

// ---------------- K1: fused [pack A]+GEMM+LIF1+bound-check+fast output -----
// tile: 32 rows x 448 cols. 8 warps: rg=w>>2 (16 rows), cs=w&3 (112 cols).
__global__ __launch_bounds__(256, 2) void k_fused(const float* __restrict__ state,
                                                  const float* __restrict__ action,
                                                  const float* __restrict__ b1,
                                                  float* __restrict__ out) {
    extern __shared__ __align__(16) unsigned char sm[];
    __nv_bfloat16* sA  = reinterpret_cast<__nv_bfloat16*>(sm + SM_A);
    __nv_bfloat16* sB0 = reinterpret_cast<__nv_bfloat16*>(sm + SM_B0);
    __nv_bfloat16* sB1 = reinterpret_cast<__nv_bfloat16*>(sm + SM_B1);
    float*    stage   = reinterpret_cast<float*>(sm);     // epilogue overlay
    unsigned* stage_u = reinterpret_cast<unsigned*>(sm);

    __shared__ float s_c[H1];
    __shared__ float s_b1[H1];
    __shared__ float s_const[ADIM];
    __shared__ float s_b2max;

    const int tid  = threadIdx.x;
    const int lane = tid & 31;
    const int w    = tid >> 5;
    const int rg   = w >> 2;
    const int cs   = w & 3;
    const int m0   = blockIdx.x * 32;

    auto load_B = [&](int c, __nv_bfloat16* dst) {
#pragma unroll
        for (int rep = 0; rep < 7; rep++) {
            int t2 = tid + rep * 256;
            int r = t2 / 56, p = t2 - r * 56;
            cp16(dst + r * SBST + 8 * p,
                 &g_W1p[(size_t)(c * KCH + r) * NPAD + 8 * p]);
        }
    };

    // kick off first B chunk immediately (overlaps A conversion)
    load_B(0, sB0);
    cp_commit();

    // constants
    for (int i = tid; i < H1; i += 256) { s_c[i] = g_c[i]; s_b1[i] = b1[i]; }
    if (tid < ADIM) s_const[tid] = g_const[tid];
    if (tid == 32)  s_b2max = g_b2max;

    // A: load fp32 state/action, convert to bf16 smem (32 x 416, stride 424)
    for (int idx = tid; idx < 32 * SDIM; idx += 256) {
        int r = idx / SDIM, c = idx - r * SDIM;
        sA[r * SAST + c] = __float2bfloat16(state[(size_t)(m0 + r) * SDIM + c]);
    }
    for (int idx = tid; idx < 32 * ADIM; idx += 256) {
        int r = idx / ADIM, c = idx - r * ADIM;
        sA[r * SAST + SDIM + c] = __float2bfloat16(action[(size_t)(m0 + r) * ADIM + c]);
    }
    for (int idx = tid; idx < 32 * (DPAD - DIN); idx += 256) {
        int r = idx / (DPAD - DIN), c = idx - r * (DPAD - DIN);
        sA[r * SAST + DIN + c] = __float2bfloat16(0.0f);
    }

    wmma::fragment<wmma::accumulator, 16, 16, 16, float> acc[7];
#pragma unroll
    for (int f = 0; f < 7; f++) wmma::fill_fragment(acc[f], 0.0f);

    for (int c = 0; c < NCHK; c++) {
        __nv_bfloat16* cur = (c & 1) ? sB1 : sB0;
        __nv_bfloat16* nxt = (c & 1) ? sB0 : sB1;
        if (c + 1 < NCHK) {
            load_B(c + 1, nxt);
            cp_commit();
            cp_wait<1>();
        } else {
            cp_wait<0>();
        }
        __syncthreads();       // also covers A-fill completion on c==0

#pragma unroll
        for (int ks = 0; ks < 2; ks++) {
            wmma::fragment<wmma::matrix_a, 16, 16, 16, __nv_bfloat16, wmma::row_major> afrag;
            wmma::load_matrix_sync(afrag,
                sA + (rg * 16) * SAST + c * KCH + ks * 16, SAST);
#pragma unroll
            for (int f = 0; f < 7; f++) {
                wmma::fragment<wmma::matrix_b, 16, 16, 16, __nv_bfloat16, wmma::row_major> bfrag;
                wmma::load_matrix_sync(bfrag,
                    cur + (ks * 16) * SBST + cs * 112 + f * 16, SBST);
                wmma::mma_sync(acc[f], afrag, bfrag, acc[f]);
            }
        }
        __syncthreads();
    }

    // ---- epilogue: stage fp32 (overlay), LIF -> word in-place, row check ----
#pragma unroll
    for (int f = 0; f < 7; f++)
        wmma::store_matrix_sync(&stage[(rg * 16) * SBST + cs * 112 + f * 16],
                                acc[f], SBST, wmma::mem_row_major);
    __syncthreads();

    for (int idx = tid; idx < 32 * H1; idx += 256) {
        int r = idx / H1;
        int c = idx - r * H1;
        float x = stage[r * SBST + c] + s_b1[c];
        unsigned word = 0u;
        if (x >= 0.999999f) {              // v_t < x always: x<1 can't spike
            float v = 0.0f;
#pragma unroll
            for (int t = 0; t < TSTEPS; t++) {
                v = fmaf(x - v, 0.5f, v);
                if (v >= 1.0f) { word |= (1u << t); v = 0.0f; }
            }
        }
        stage_u[r * SBST + c] = word;
    }
    __syncthreads();

    // per-row check: warp w handles rows w*4 .. w*4+3
#pragma unroll
    for (int rr = 0; rr < 4; rr++) {
        int r = w * 4 + rr;
        int grow = m0 + r;
        float accu = 0.0f;                 // lane = timestep
        for (int ch = 0; ch < 13; ch++) {
            int i = ch * 32 + lane;
            unsigned word = (i < H1) ? stage_u[r * SBST + i] : 0u;
            unsigned bal = __ballot_sync(0xffffffffu, word != 0u);
            while (bal) {
                int b = __ffs(bal) - 1;
                bal &= bal - 1;
                unsigned wb = __shfl_sync(0xffffffffu, word, b);
                float ci = s_c[ch * 32 + b];
                if ((wb >> lane) & 1u) accu += ci;
            }
        }
        // TIGHT bound: LIF-2 recurrence on per-timestep upper bounds.
        float u = s_b2max + accu;          // this lane's timestep bound
        float vb = 0.0f, vbmax = -3.4e38f;
#pragma unroll
        for (int t = 0; t < TSTEPS; t++) {
            float ut = __shfl_sync(0xffffffffu, u, t);
            vb = 0.5f * (vb + ut);
            vbmax = fmaxf(vbmax, vb);
        }
        int slow = (vbmax >= 1.0f);

        if (!slow) {
            if (lane < ADIM) {
                float o = s_const[lane] + action[(size_t)grow * ADIM + lane];
                out[(size_t)grow * ADIM + lane] = fminf(fmaxf(o, -1.0f), 1.0f);
            }
        } else {
            for (int ch = 0; ch < 13; ch++) {
                int i = ch * 32 + lane;
                if (i < H1)
                    g_S1[(size_t)grow * H1 + i] = stage_u[r * SBST + i];
            }
            if (lane == 0) {
                int s = atomicAdd(&g_nslow, 1);
                g_slowlist[s] = grow;
            }
        }
    }
}

// ---------------- K2: exact slow path, register-accumulator layer 2 --------
__global__ __launch_bounds__(320) void k_snn(const float* __restrict__ action,
                                             const float* __restrict__ W2,
                                             const float* __restrict__ b2,
                                             const float* __restrict__ W3,
                                             const float* __restrict__ b3,
                                             float* __restrict__ out) {
    __shared__ unsigned       s_mask1[H1];
    __shared__ unsigned short s_fire[H1];
    __shared__ unsigned       s_msk[H1];          // compacted masks
    __shared__ unsigned       s_mask2[H2];
    __shared__ unsigned short s_list2[TSTEPS][CAP2];
    __shared__ int            s_cnt2[TSTEPS];
    __shared__ int            s_nf;

    int tid  = threadIdx.x;
    int lane = tid & 31;
    int w    = tid >> 5;
    unsigned lmask = (1u << lane) - 1u;
    int nslow = g_nslow;

    for (int s = blockIdx.x; s < nslow; s += gridDim.x) {
        int row = g_slowlist[s];

        for (int i = tid; i < H1; i += 320)
            s_mask1[i] = g_S1[(size_t)row * H1 + i];
        __syncthreads();

        if (w == 0) {
            int nf = 0;
            for (int c = 0; c * 32 < H1; c++) {
                int i = c * 32 + lane;
                unsigned m = (i < H1) ? s_mask1[i] : 0u;
                int pred = (m != 0u);
                unsigned bal = __ballot_sync(0xffffffffu, pred);
                int pos = nf + __popc(bal & lmask);
                if (pred) { s_fire[pos] = (unsigned short)i; s_msk[pos] = m; }
                nf += __popc(bal);
            }
            if (lane == 0) s_nf = nf;
        }
        __syncthreads();
        int nf = s_nf;

        // layer 2: each j-thread keeps 32 per-timestep accumulators in regs.
        // One coalesced, MLP-pipelined W2 row load per firing neuron.
        if (tid < H2) {
            int j = tid;
            float a[TSTEPS];
#pragma unroll
            for (int t = 0; t < TSTEPS; t++) a[t] = 0.0f;

#pragma unroll 4
            for (int q = 0; q < nf; q++) {
                float wv = W2[(size_t)s_fire[q] * H2 + j];
                unsigned m = s_msk[q];
#pragma unroll
                for (int t = 0; t < TSTEPS; t++)
                    if ((m >> t) & 1u) a[t] += wv;
            }

            float b2j = b2[j];
            float v2 = 0.0f;
            unsigned mask2 = 0u;
#pragma unroll
            for (int t = 0; t < TSTEPS; t++) {
                float x2 = b2j + a[t];
                v2 += (x2 - v2) * 0.5f;
                if (v2 >= 1.0f) { mask2 |= (1u << t); v2 = 0.0f; }
            }
            s_mask2[j] = mask2;
        }
        __syncthreads();

        // per-timestep layer-2 firing lists
        for (int t = w; t < TSTEPS; t += 10) {
            int cnt = 0;
            for (int c = 0; c * 32 < H2; c++) {
                int j = c * 32 + lane;
                int pred = 0;
                if (j < H2) pred = (int)((s_mask2[j] >> t) & 1u);
                unsigned bal = __ballot_sync(0xffffffffu, pred);
                int pos = cnt + __popc(bal & lmask);
                if (pred && pos < CAP2) s_list2[t][pos] = (unsigned short)j;
                cnt += __popc(bal);
            }
            s_cnt2[t] = cnt < CAP2 ? cnt : CAP2;
        }
        __syncthreads();

        // layer 3 (non-spiking) + epilogue
        if (tid < ADIM) {
            int k = tid;
            float b3k = b3[k];
            float v3 = 0.0f, vmax = -3.4e38f;
            for (int t = 0; t < TSTEPS; t++) {
                float x3 = b3k;
                int n = s_cnt2[t];
                for (int q = 0; q < n; q++) {
                    int j = s_list2[t][q];
                    x3 += W3[j * ADIM + k];
                }
                v3 += (x3 - v3) * 0.5f;
                vmax = fmaxf(vmax, v3);
            }
            float a2 = 0.05f * tanhf(vmax);
            float o = a2 + action[(size_t)row * ADIM + k];
            o = fminf(fmaxf(o, -1.0f), 1.0f);
            out[(size_t)row * ADIM + k] = o;
        }
        __syncthreads();
    }
}

// ---------------- launch ----------------
extern "C" void kernel_launch(void* const* d_in, const int* in_sizes, int n_in,
                              void* d_out, int out_size) {
    (void)in_sizes; (void)n_in; (void)out_size;
    const float* state  = (const float*)d_in[0];
    const float* action = (const float*)d_in[1];
    const float* W1     = (const float*)d_in[2];
    const float* b1     = (const float*)d_in[3];
    const float* W2     = (const float*)d_in[4];
    const float* b2     = (const float*)d_in[5];
    const float* W3     = (const float*)d_in[6];
    const float* b3     = (const float*)d_in[7];
    float* out = (float*)d_out;

    cudaFuncSetAttribute(k_fused, cudaFuncAttributeMaxDynamicSharedMemorySize,
                         SM_DYN);

    k_pack_w1<<<(DPAD * NPAD + 255) / 256, 256>>>(W1);
    k_prep<<<H1 + 1, 32>>>(W2, b2, b3);

    k_fused<<<BATCH / 32, 256, SM_DYN>>>(state, action, b1, out);

    k_snn<<<1024, 320>>>(action, W2, b2, W3, b3, out);
}